// round 11
// baseline (speedup 1.0000x reference)
#include <cuda_runtime.h>
#include <cstdint>

// Lanczos upsample (4,2,256,256) f32 -> (4,2,2048,2048) f32, 8x per axis.
//
// Algebra (validated, rel_err ~1.4e-7): reference nearest-gather + 9-tap
// LUT-Lanczos collapses to a 2x2 weighted gather with 8 compile-time phase
// weight pairs per axis; reflect padding == clamp to boundary source pixel.
//
// Round 11: 8-row groups, two 32KB bulk stores into DISJOINT 32KB buffers
// (64KB dynamic smem) -- no buffer reuse, so no intermediate wait_group
// stalls; only the final read-wait remains. Grid 4096 -> 2048. evict_first
// retained (proved a wall-time win in R10). The kernel family is at the
// steady-state DRAM write-stream ceiling (~6 TB/s); this targets the
// residual per-block tail/overhead.

namespace lw {

constexpr double PI = 3.14159265358979323846;

constexpr double csin(double x) {
    double k = x / (2.0 * PI);
    long long n = (long long)(k >= 0.0 ? k + 0.5 : k - 0.5);
    double r = x - (double)n * (2.0 * PI);
    if (r > PI * 0.5)       r =  PI - r;
    else if (r < -PI * 0.5) r = -PI - r;
    double term = r, sum = r;
    const double r2 = r * r;
    for (int i = 1; i <= 11; ++i) {
        term *= -r2 / ((2.0 * i) * (2.0 * i + 1.0));
        sum += term;
    }
    return sum;
}

constexpr double tap(double d, int p) {
    double t  = d + (double)(p - 4);
    double tp = t * PI;
    double tq = tp * 0.25;
    return (csin(tp) / tp) * (csin(tq) / tq);
}

constexpr float wA(int f) {
    double d = 1e-8 + (double)f / 8.0;
    int r = (f + 4) & 7;
    double a = 0.0;
    for (int p = 0; p < 8 - r; ++p) a += tap(d, p);
    return (float)a;
}
constexpr float wB(int f) {
    double d = 1e-8 + (double)f / 8.0;
    int r = (f + 4) & 7;
    double b = 0.0;
    for (int p = 8 - r; p <= 8; ++p) b += tap(d, p);
    return (float)b;
}

} // namespace lw

// Scalar host constexprs fold into device code as literals (proven pattern).
constexpr float A0 = lw::wA(0), A1 = lw::wA(1), A2 = lw::wA(2), A3 = lw::wA(3);
constexpr float A4 = lw::wA(4), A5 = lw::wA(5), A6 = lw::wA(6), A7 = lw::wA(7);
constexpr float B0 = lw::wB(0), B1 = lw::wB(1), B2 = lw::wB(2), B3 = lw::wB(3);
constexpr float B4 = lw::wB(4), B5 = lw::wB(5), B6 = lw::wB(6), B7 = lw::wB(7);

template <int F> __device__ __forceinline__ constexpr float getA() {
    if constexpr (F == 0) return A0; else if constexpr (F == 1) return A1;
    else if constexpr (F == 2) return A2; else if constexpr (F == 3) return A3;
    else if constexpr (F == 4) return A4; else if constexpr (F == 5) return A5;
    else if constexpr (F == 6) return A6; else return A7;
}
template <int F> __device__ __forceinline__ constexpr float getB() {
    if constexpr (F == 0) return B0; else if constexpr (F == 1) return B1;
    else if constexpr (F == 2) return B2; else if constexpr (F == 3) return B3;
    else if constexpr (F == 4) return B4; else if constexpr (F == 5) return B5;
    else if constexpr (F == 6) return B6; else return B7;
}

__device__ __forceinline__ uint32_t smem_u32(const void* p) {
    uint32_t a;
    asm("{ .reg .u64 t; cvta.to.shared.u64 t, %1; cvt.u32.u64 %0, t; }"
        : "=r"(a) : "l"(p));
    return a;
}

// Compute row at y-phase FY (compile time) into smem. x-phases 0..3 use
// source cols (k-1,k); 4..7 use (k,k+1).
template <int FY>
__device__ __forceinline__ void compute_row(
    float* __restrict__ srow, int k,
    float s00, float s01, float s02, float s10, float s11, float s12)
{
    constexpr float Ay = getA<FY>();
    constexpr float By = getB<FY>();

    const float v0 = Ay * s00 + By * s10;
    const float v1 = Ay * s01 + By * s11;
    const float v2 = Ay * s02 + By * s12;

    float4 o0, o1;
    o0.x = A0 * v0 + B0 * v1;
    o0.y = A1 * v0 + B1 * v1;
    o0.z = A2 * v0 + B2 * v1;
    o0.w = A3 * v0 + B3 * v1;
    o1.x = A4 * v1 + B4 * v2;
    o1.y = A5 * v1 + B5 * v2;
    o1.z = A6 * v1 + B6 * v2;
    o1.w = A7 * v1 + B7 * v2;

    float4* sp = reinterpret_cast<float4*>(srow + k * 8);
    sp[0] = o0;
    sp[1] = o1;
}

__device__ __forceinline__ void bulk_commit32k(const float* sbuf, float* gdst) {
    // Caller guarantees a preceding __syncthreads; thread 0 only.
    asm volatile("fence.proxy.async.shared::cta;" ::: "memory");
    unsigned long long policy;
    asm volatile("createpolicy.fractional.L2::evict_first.b64 %0, 1.0;"
                 : "=l"(policy));
    asm volatile(
        "cp.async.bulk.global.shared::cta.bulk_group.L2::cache_hint"
        " [%0], [%1], %2, %3;"
        :: "l"((unsigned long long)gdst), "r"(smem_u32(sbuf)),
           "n"(32768), "l"(policy) : "memory");
    asm volatile("cp.async.bulk.commit_group;" ::: "memory");
}

// Grid: 8 channels x 256 eight-row groups. Block (bc,g) emits output rows
// y = 8g..8g+7: phases 0..3 blend source rows (g-1,g) clamped, phases 4..7
// blend (g,g+1) clamped. Thread k owns output columns 8k..8k+7 from source
// columns k-1,k,k+1. Two disjoint 32KB smem buffers -> two bulk stores, no
// reuse waits.
__global__ void __launch_bounds__(256)
lz_upsample_kernel(const float* __restrict__ img, float* __restrict__ out) {
    extern __shared__ __align__(128) float buf[];   // 2 x 8192 floats = 64 KB

    const int b  = blockIdx.x;
    const int bc = b >> 8;
    const int g  = b & 255;

    const int ra = max(g - 1, 0);
    const int rc = min(g + 1, 255);

    const float* __restrict__ base = img + (size_t)bc * 65536;
    const float* __restrict__ pa = base + ra * 256;
    const float* __restrict__ pb = base + g  * 256;
    const float* __restrict__ pc = base + rc * 256;

    const int k  = threadIdx.x;
    const int km = max(k - 1, 0);
    const int kp = min(k + 1, 255);

    const float a0 = __ldg(pa + km), a1 = __ldg(pa + k), a2 = __ldg(pa + kp);
    const float b0 = __ldg(pb + km), b1 = __ldg(pb + k), b2 = __ldg(pb + kp);
    const float c0 = __ldg(pc + km), c1 = __ldg(pc + k), c2 = __ldg(pc + kp);

    float* const gbase = out + ((size_t)bc * 2048 + (size_t)(8 * g)) * 2048;
    const bool t0 = (threadIdx.x == 0);

    float* const buf0 = buf;
    float* const buf1 = buf + 8192;

    // Chunk 0: rows 8g+0..8g+3 (phases 0..3; pair a,b) -> buf0, commit.
    compute_row<0>(buf0,            k, a0, a1, a2, b0, b1, b2);
    compute_row<1>(buf0 + 2048,     k, a0, a1, a2, b0, b1, b2);
    compute_row<2>(buf0 + 2 * 2048, k, a0, a1, a2, b0, b1, b2);
    compute_row<3>(buf0 + 3 * 2048, k, a0, a1, a2, b0, b1, b2);
    __syncthreads();
    if (t0) bulk_commit32k(buf0, gbase);

    // Chunk 1: rows 8g+4..8g+7 (phases 4..7; pair b,c) -> buf1, commit.
    // Computed while the engine drains buf0; buffers disjoint, no reuse wait.
    compute_row<4>(buf1,            k, b0, b1, b2, c0, c1, c2);
    compute_row<5>(buf1 + 2048,     k, b0, b1, b2, c0, c1, c2);
    compute_row<6>(buf1 + 2 * 2048, k, b0, b1, b2, c0, c1, c2);
    compute_row<7>(buf1 + 3 * 2048, k, b0, b1, b2, c0, c1, c2);
    __syncthreads();
    if (t0) {
        bulk_commit32k(buf1, gbase + 4 * 2048);
        // Block must not exit until the engine has READ all smem.
        asm volatile("cp.async.bulk.wait_group.read 0;" ::: "memory");
    }
}

extern "C" void kernel_launch(void* const* d_in, const int* in_sizes, int n_in,
                              void* d_out, int out_size) {
    (void)in_sizes; (void)n_in; (void)out_size;
    const float* img = (const float*)d_in[0];
    float* out = (float*)d_out;

    // Capture-safe (host attribute set; not a stream op, no allocation).
    cudaFuncSetAttribute(lz_upsample_kernel,
                         cudaFuncAttributeMaxDynamicSharedMemorySize, 65536);

    lz_upsample_kernel<<<8 * 256, 256, 65536>>>(img, out);
}

// round 13
// speedup vs baseline: 1.0132x; 1.0132x over previous
#include <cuda_runtime.h>
#include <cstdint>

// Lanczos upsample (4,2,256,256) f32 -> (4,2,2048,2048) f32, 8x per axis.
//
// FINAL FORM (R10 reversion). Algebra (validated, rel_err ~1.4e-7): the
// reference's nearest-gather + 9-tap LUT-Lanczos on the upsampled grid
// collapses to a 2x2 weighted gather with 8 compile-time phase weight pairs
// per axis; reflect padding == clamp to the boundary source pixel.
//
// Egress: one 32KB cp.async.bulk per block (4 contiguous output rows) with
// L2 evict_first. History: per-thread STG (34.8us) -> bulk store (28.6) ->
// 4-row span (26.6) -> +evict_first (24.4 = best). Schedule variants
// (pipelined drains R8, dual-engine R9, disjoint-buffer R11) and
// discard.global.L2 (R12: UNSAFE, corrupts) all failed to beat it: the
// kernel sits at the steady-state DRAM write-stream floor (~6 TB/s).

namespace lw {

constexpr double PI = 3.14159265358979323846;

constexpr double csin(double x) {
    double k = x / (2.0 * PI);
    long long n = (long long)(k >= 0.0 ? k + 0.5 : k - 0.5);
    double r = x - (double)n * (2.0 * PI);
    if (r > PI * 0.5)       r =  PI - r;
    else if (r < -PI * 0.5) r = -PI - r;
    double term = r, sum = r;
    const double r2 = r * r;
    for (int i = 1; i <= 11; ++i) {
        term *= -r2 / ((2.0 * i) * (2.0 * i + 1.0));
        sum += term;
    }
    return sum;
}

constexpr double tap(double d, int p) {
    double t  = d + (double)(p - 4);
    double tp = t * PI;
    double tq = tp * 0.25;
    return (csin(tp) / tp) * (csin(tq) / tq);
}

constexpr float wA(int f) {
    double d = 1e-8 + (double)f / 8.0;
    int r = (f + 4) & 7;
    double a = 0.0;
    for (int p = 0; p < 8 - r; ++p) a += tap(d, p);
    return (float)a;
}
constexpr float wB(int f) {
    double d = 1e-8 + (double)f / 8.0;
    int r = (f + 4) & 7;
    double b = 0.0;
    for (int p = 8 - r; p <= 8; ++p) b += tap(d, p);
    return (float)b;
}

} // namespace lw

// Scalar host constexprs fold into device code as literals (proven pattern).
constexpr float A0 = lw::wA(0), A1 = lw::wA(1), A2 = lw::wA(2), A3 = lw::wA(3);
constexpr float A4 = lw::wA(4), A5 = lw::wA(5), A6 = lw::wA(6), A7 = lw::wA(7);
constexpr float B0 = lw::wB(0), B1 = lw::wB(1), B2 = lw::wB(2), B3 = lw::wB(3);
constexpr float B4 = lw::wB(4), B5 = lw::wB(5), B6 = lw::wB(6), B7 = lw::wB(7);

template <int F> __device__ __forceinline__ constexpr float getA() {
    if constexpr (F == 0) return A0; else if constexpr (F == 1) return A1;
    else if constexpr (F == 2) return A2; else if constexpr (F == 3) return A3;
    else if constexpr (F == 4) return A4; else if constexpr (F == 5) return A5;
    else if constexpr (F == 6) return A6; else return A7;
}
template <int F> __device__ __forceinline__ constexpr float getB() {
    if constexpr (F == 0) return B0; else if constexpr (F == 1) return B1;
    else if constexpr (F == 2) return B2; else if constexpr (F == 3) return B3;
    else if constexpr (F == 4) return B4; else if constexpr (F == 5) return B5;
    else if constexpr (F == 6) return B6; else return B7;
}

__device__ __forceinline__ uint32_t smem_u32(const void* p) {
    uint32_t a;
    asm("{ .reg .u64 t; cvta.to.shared.u64 t, %1; cvt.u32.u64 %0, t; }"
        : "=r"(a) : "l"(p));
    return a;
}

// Compute row at y-phase FY (compile time) into smem. x-phases 0..3 use
// source cols (k-1,k); 4..7 use (k,k+1).
template <int FY>
__device__ __forceinline__ void compute_row(
    float* __restrict__ srow, int k,
    float s00, float s01, float s02, float s10, float s11, float s12)
{
    constexpr float Ay = getA<FY>();
    constexpr float By = getB<FY>();

    const float v0 = Ay * s00 + By * s10;
    const float v1 = Ay * s01 + By * s11;
    const float v2 = Ay * s02 + By * s12;

    float4 o0, o1;
    o0.x = A0 * v0 + B0 * v1;
    o0.y = A1 * v0 + B1 * v1;
    o0.z = A2 * v0 + B2 * v1;
    o0.w = A3 * v0 + B3 * v1;
    o1.x = A4 * v1 + B4 * v2;
    o1.y = A5 * v1 + B5 * v2;
    o1.z = A6 * v1 + B6 * v2;
    o1.w = A7 * v1 + B7 * v2;

    float4* sp = reinterpret_cast<float4*>(srow + k * 8);
    sp[0] = o0;
    sp[1] = o1;
}

// Grid: 8 channels x 512 four-row spans. Block (bc, m) produces output rows
// y = 4m..4m+3 (contiguous 32KB), all blending source rows ry0=clamp((4m-4)>>3)
// and ry1=ry0+1 clamped. Thread k owns output columns 8k..8k+7 from source
// columns k-1,k,k+1.
__global__ void __launch_bounds__(256)
lz_upsample_kernel(const float* __restrict__ img, float* __restrict__ out) {
    __shared__ __align__(128) float rowbuf[4][2048];   // 32 KB

    const int b  = blockIdx.x;
    const int bc = b >> 9;               // channel 0..7
    const int m  = b & 511;              // 4-row span index

    const int y0   = 4 * m;
    const int ry0u = (y0 - 4) >> 3;      // constant across the span
    const int ry0  = max(ry0u, 0);
    const int ry1  = min(ry0u + 1, 255);

    const float* __restrict__ base = img + (size_t)bc * 65536;
    const float* __restrict__ r0   = base + ry0 * 256;
    const float* __restrict__ r1   = base + ry1 * 256;

    const int k  = threadIdx.x;
    const int km = max(k - 1, 0);
    const int kp = min(k + 1, 255);

    const float s00 = __ldg(r0 + km), s01 = __ldg(r0 + k), s02 = __ldg(r0 + kp);
    const float s10 = __ldg(r1 + km), s11 = __ldg(r1 + k), s12 = __ldg(r1 + kp);

    if (m & 1) {   // y-phases 4..7
        compute_row<4>(rowbuf[0], k, s00, s01, s02, s10, s11, s12);
        compute_row<5>(rowbuf[1], k, s00, s01, s02, s10, s11, s12);
        compute_row<6>(rowbuf[2], k, s00, s01, s02, s10, s11, s12);
        compute_row<7>(rowbuf[3], k, s00, s01, s02, s10, s11, s12);
    } else {       // y-phases 0..3
        compute_row<0>(rowbuf[0], k, s00, s01, s02, s10, s11, s12);
        compute_row<1>(rowbuf[1], k, s00, s01, s02, s10, s11, s12);
        compute_row<2>(rowbuf[2], k, s00, s01, s02, s10, s11, s12);
        compute_row<3>(rowbuf[3], k, s00, s01, s02, s10, s11, s12);
    }

    __syncthreads();

    if (threadIdx.x == 0) {
        // Order generic-proxy STS before the async-proxy bulk read.
        asm volatile("fence.proxy.async.shared::cta;" ::: "memory");
        const unsigned long long gdst =
            (unsigned long long)(out + ((size_t)bc * 2048 + (size_t)y0) * 2048);
        const uint32_t ssrc = smem_u32(rowbuf);
        // evict_first: output is never re-read; drain dirty lines eagerly so
        // steady-state replay doesn't burst-evict against the write wall.
        unsigned long long policy;
        asm volatile("createpolicy.fractional.L2::evict_first.b64 %0, 1.0;"
                     : "=l"(policy));
        asm volatile(
            "cp.async.bulk.global.shared::cta.bulk_group.L2::cache_hint"
            " [%0], [%1], %2, %3;"
            :: "l"(gdst), "r"(ssrc), "n"(32768), "l"(policy) : "memory");
        asm volatile("cp.async.bulk.commit_group;" ::: "memory");
        // Block must not exit until the engine has READ the smem buffer.
        asm volatile("cp.async.bulk.wait_group.read 0;" ::: "memory");
    }
}

extern "C" void kernel_launch(void* const* d_in, const int* in_sizes, int n_in,
                              void* d_out, int out_size) {
    (void)in_sizes; (void)n_in; (void)out_size;
    const float* img = (const float*)d_in[0];
    float* out = (float*)d_out;

    lz_upsample_kernel<<<8 * 512, 256>>>(img, out);
}